// round 1
// baseline (speedup 1.0000x reference)
#include <cuda_runtime.h>

// ---------------------------------------------------------------------------
// PointGiraffeLayer: 3-NN interpolate -> FC(BN,ReLU) -> 3-NN interpolate -> FC
// Shapes (fixed): B=2, N1=8192, N2=4096, N4=2048, C=128
// Inputs (metadata order):
//  0 pts_r1 (B,N1,3) 1 pts_r2 (B,N2,3) 2 pts_r4 (B,N4,3)
//  3 feat0 (B*N1,128) 4 feat1 (B*N2,128) 5 feat2 (B*N4,128)
//  6 w3a(128,256) 7 g3(128) 8 b3(128) 9 w3b(128,128) 10 bb3(128)
// 11 w4a(128,256) 12 g4 13 b4 14 w4b(128,128) 15 bb4
// Output: (B*N1, 128) f32
// ---------------------------------------------------------------------------

#define CCH 128

// Scratch (device globals -- no allocation allowed)
__device__ float g_f2i[2 * 4096 * CCH];   // interp(feat2 -> r2 grid)
__device__ float g_h3 [2 * 4096 * CCH];   // fc3 hidden (pre-BN)
__device__ float g_n3 [2 * 4096 * CCH];   // fc3 out
__device__ float g_n3i[2 * 8192 * CCH];   // interp(n3 -> r1 grid)
__device__ float g_h4 [2 * 8192 * CCH];   // fc4 hidden (pre-BN)
__device__ float g_psum[128 * 128];       // per-block column sums
__device__ float g_psq [128 * 128];       // per-block column sumsq
__device__ float g_scale[128];
__device__ float g_shift[128];

// ---------------------------------------------------------------------------
// 3-NN interpolation. One warp handles TPW targets; sources cached in smem.
// ---------------------------------------------------------------------------
__device__ __forceinline__ void ins3(float d, int s,
                                     float& d0, int& i0,
                                     float& d1, int& i1,
                                     float& d2, int& i2) {
    if (d < d2) {
        if (d < d1) {
            d2 = d1; i2 = i1;
            if (d < d0) { d1 = d0; i1 = i0; d0 = d; i0 = s; }
            else        { d1 = d;  i1 = s; }
        } else { d2 = d; i2 = s; }
    }
}

constexpr int IWARPS = 8;   // warps per block
constexpr int TPW    = 4;   // targets per warp

__global__ void interp3nn(const float* __restrict__ src_xyz,   // (B,NS,3)
                          const float* __restrict__ tgt_xyz,   // (B,NT,3)
                          const float* __restrict__ feats,     // (B*NS,128)
                          float* __restrict__ out,             // (B*NT,128)
                          int NS, int NT) {
    extern __shared__ float smem[];
    float* sx = smem;
    float* sy = smem + NS;
    float* sz = smem + 2 * NS;

    const int b = blockIdx.y;
    const float* S = src_xyz + (size_t)b * NS * 3;
    for (int i = threadIdx.x; i < NS; i += blockDim.x) {
        sx[i] = S[3 * i + 0];
        sy[i] = S[3 * i + 1];
        sz[i] = S[3 * i + 2];
    }
    __syncthreads();

    const int warp = threadIdx.x >> 5;
    const int lane = threadIdx.x & 31;
    const int tbase = (blockIdx.x * IWARPS + warp) * TPW;
    if (tbase >= NT) return;

    float tx[TPW], ty[TPW], tz[TPW];
    float d0[TPW], d1[TPW], d2[TPW];
    int   i0[TPW], i1[TPW], i2[TPW];
#pragma unroll
    for (int j = 0; j < TPW; j++) {
        int t = min(tbase + j, NT - 1);
        const float* T = tgt_xyz + ((size_t)b * NT + t) * 3;
        tx[j] = T[0]; ty[j] = T[1]; tz[j] = T[2];
        d0[j] = d1[j] = d2[j] = 3.4e38f;
        i0[j] = i1[j] = i2[j] = 0;
    }

    for (int s = lane; s < NS; s += 32) {
        float x = sx[s], y = sy[s], z = sz[s];
#pragma unroll
        for (int j = 0; j < TPW; j++) {
            float dx = tx[j] - x, dy = ty[j] - y, dz = tz[j] - z;
            float d = dx * dx + dy * dy + dz * dz;
            ins3(d, s, d0[j], i0[j], d1[j], i1[j], d2[j], i2[j]);
        }
    }

    // butterfly merge of sorted triples across the warp
#pragma unroll
    for (int j = 0; j < TPW; j++) {
#pragma unroll
        for (int off = 16; off > 0; off >>= 1) {
            float od0 = __shfl_xor_sync(0xffffffffu, d0[j], off);
            int   oi0 = __shfl_xor_sync(0xffffffffu, i0[j], off);
            float od1 = __shfl_xor_sync(0xffffffffu, d1[j], off);
            int   oi1 = __shfl_xor_sync(0xffffffffu, i1[j], off);
            float od2 = __shfl_xor_sync(0xffffffffu, d2[j], off);
            int   oi2 = __shfl_xor_sync(0xffffffffu, i2[j], off);
            ins3(od0, oi0, d0[j], i0[j], d1[j], i1[j], d2[j], i2[j]);
            ins3(od1, oi1, d0[j], i0[j], d1[j], i1[j], d2[j], i2[j]);
            ins3(od2, oi2, d0[j], i0[j], d1[j], i1[j], d2[j], i2[j]);
        }
    }

    // weights + 3-row gather (float4 per lane: 32 lanes * 4 = 128 channels)
#pragma unroll
    for (int j = 0; j < TPW; j++) {
        int t = tbase + j;
        if (t >= NT) break;
        float s0 = sqrtf(fmaxf(d0[j], 0.f));
        float s1 = sqrtf(fmaxf(d1[j], 0.f));
        float s2 = sqrtf(fmaxf(d2[j], 0.f));
        float w0 = 1.f / (s0 + 1e-8f);
        float w1 = 1.f / (s1 + 1e-8f);
        float w2 = 1.f / (s2 + 1e-8f);
        float wi = 1.f / (w0 + w1 + w2);
        w0 *= wi; w1 *= wi; w2 *= wi;

        const float4* f0 = (const float4*)(feats + ((size_t)b * NS + i0[j]) * CCH);
        const float4* f1 = (const float4*)(feats + ((size_t)b * NS + i1[j]) * CCH);
        const float4* f2 = (const float4*)(feats + ((size_t)b * NS + i2[j]) * CCH);
        float4 a = f0[lane], bb = f1[lane], cc = f2[lane];
        float4 r;
        r.x = w0 * a.x + w1 * bb.x + w2 * cc.x;
        r.y = w0 * a.y + w1 * bb.y + w2 * cc.y;
        r.z = w0 * a.z + w1 * bb.z + w2 * cc.z;
        r.w = w0 * a.w + w1 * bb.w + w2 * cc.w;
        ((float4*)(out + ((size_t)b * NT + t) * CCH))[lane] = r;
    }
}

// ---------------------------------------------------------------------------
// Tiled SGEMM: C (N x 128) = X (N x KD) @ W^T  (W is (128, KD) row-major)
// SPLIT : X = concat(A0, A1) along K (each N x 128)
// AFFINE: x -> relu(x * scale[k] + shift[k]) applied on load (BN+ReLU fusion)
// SUMS  : emit per-block column sum / sumsq of C (pre-bias) -> BN stats
// BIAS  : add bias[col] at epilogue
// Requires N % 128 == 0. Block: 256 threads, tile 128x128x16, 8x8 per thread.
// ---------------------------------------------------------------------------
template <int KD, bool SPLIT, bool AFFINE, bool SUMS, bool BIAS>
__global__ void gemm128(const float* __restrict__ A0, const float* __restrict__ A1,
                        const float* __restrict__ W,
                        const float* __restrict__ scale, const float* __restrict__ shift,
                        const float* __restrict__ bias,
                        float* __restrict__ Cout,
                        float* __restrict__ psum, float* __restrict__ psq) {
    __shared__ float As[16][128];
    __shared__ float Bs[16][128];

    const int t  = threadIdx.x;
    const int tx = t & 15;        // 16 col groups
    const int ty = t >> 4;        // 16 row groups
    const int blockRow = blockIdx.x * 128;

    float acc[8][8];
#pragma unroll
    for (int i = 0; i < 8; i++)
#pragma unroll
        for (int j = 0; j < 8; j++) acc[i][j] = 0.f;

    for (int k0 = 0; k0 < KD; k0 += 16) {
        // --- load A tile (transposed into As[k][m]) ---
#pragma unroll
        for (int i = 0; i < 2; i++) {
            int idx = t + i * 256;          // float4 slot
            int row = idx >> 2;
            int kq  = (idx & 3) << 2;
            int kg  = k0 + kq;
            const float* src;
            if (SPLIT) {
                src = (kg < 128) ? (A0 + (size_t)(blockRow + row) * 128 + kg)
                                 : (A1 + (size_t)(blockRow + row) * 128 + (kg - 128));
            } else {
                src = A0 + (size_t)(blockRow + row) * KD + kg;
            }
            float4 v = *(const float4*)src;
            if (AFFINE) {
                v.x = fmaxf(v.x * scale[kg + 0] + shift[kg + 0], 0.f);
                v.y = fmaxf(v.y * scale[kg + 1] + shift[kg + 1], 0.f);
                v.z = fmaxf(v.z * scale[kg + 2] + shift[kg + 2], 0.f);
                v.w = fmaxf(v.w * scale[kg + 3] + shift[kg + 3], 0.f);
            }
            As[kq + 0][row] = v.x;
            As[kq + 1][row] = v.y;
            As[kq + 2][row] = v.z;
            As[kq + 3][row] = v.w;
        }
        // --- load B tile (W^T) ---
#pragma unroll
        for (int i = 0; i < 2; i++) {
            int idx = t + i * 256;
            int oc  = idx >> 2;
            int kq  = (idx & 3) << 2;
            float4 v = *(const float4*)(W + (size_t)oc * KD + k0 + kq);
            Bs[kq + 0][oc] = v.x;
            Bs[kq + 1][oc] = v.y;
            Bs[kq + 2][oc] = v.z;
            Bs[kq + 3][oc] = v.w;
        }
        __syncthreads();

#pragma unroll
        for (int k = 0; k < 16; k++) {
            float4 a0 = *(const float4*)&As[k][ty * 8];
            float4 a1 = *(const float4*)&As[k][ty * 8 + 4];
            float4 b0 = *(const float4*)&Bs[k][tx * 8];
            float4 b1 = *(const float4*)&Bs[k][tx * 8 + 4];
            float ar[8] = {a0.x, a0.y, a0.z, a0.w, a1.x, a1.y, a1.z, a1.w};
            float br[8] = {b0.x, b0.y, b0.z, b0.w, b1.x, b1.y, b1.z, b1.w};
#pragma unroll
            for (int i = 0; i < 8; i++)
#pragma unroll
                for (int j = 0; j < 8; j++) acc[i][j] += ar[i] * br[j];
        }
        __syncthreads();
    }

    // --- epilogue: store ---
    const int r0 = blockRow + ty * 8;
    const int c0 = tx * 8;
#pragma unroll
    for (int i = 0; i < 8; i++) {
        float4 v0, v1;
        v0.x = acc[i][0]; v0.y = acc[i][1]; v0.z = acc[i][2]; v0.w = acc[i][3];
        v1.x = acc[i][4]; v1.y = acc[i][5]; v1.z = acc[i][6]; v1.w = acc[i][7];
        if (BIAS) {
            v0.x += bias[c0 + 0]; v0.y += bias[c0 + 1]; v0.z += bias[c0 + 2]; v0.w += bias[c0 + 3];
            v1.x += bias[c0 + 4]; v1.y += bias[c0 + 5]; v1.z += bias[c0 + 6]; v1.w += bias[c0 + 7];
        }
        *(float4*)(Cout + (size_t)(r0 + i) * 128 + c0)     = v0;
        *(float4*)(Cout + (size_t)(r0 + i) * 128 + c0 + 4) = v1;
    }

    // --- deterministic per-block BN partials (pre-bias values) ---
    if (SUMS) {
        float cs[8], cq[8];
#pragma unroll
        for (int j = 0; j < 8; j++) {
            float s = 0.f, q = 0.f;
#pragma unroll
            for (int i = 0; i < 8; i++) { s += acc[i][j]; q += acc[i][j] * acc[i][j]; }
            cs[j] = s; cq[j] = q;
        }
        __syncthreads();
#pragma unroll
        for (int j = 0; j < 8; j++) As[ty][c0 + j] = cs[j];
        __syncthreads();
        if (t < 128) {
            float s = 0.f;
#pragma unroll
            for (int y = 0; y < 16; y++) s += As[y][t];
            psum[blockIdx.x * 128 + t] = s;
        }
        __syncthreads();
#pragma unroll
        for (int j = 0; j < 8; j++) As[ty][c0 + j] = cq[j];
        __syncthreads();
        if (t < 128) {
            float s = 0.f;
#pragma unroll
            for (int y = 0; y < 16; y++) s += As[y][t];
            psq[blockIdx.x * 128 + t] = s;
        }
    }
}

// ---------------------------------------------------------------------------
// BN finalize: mean/var from partials -> (scale, shift) for fused affine+ReLU
// ---------------------------------------------------------------------------
__global__ void bn_finalize(const float* __restrict__ psum, const float* __restrict__ psq,
                            int nchunks, float invN,
                            const float* __restrict__ g, const float* __restrict__ b,
                            float* __restrict__ scale, float* __restrict__ shift) {
    int c = threadIdx.x;
    float s = 0.f, q = 0.f;
    for (int k = 0; k < nchunks; k++) {
        s += psum[k * 128 + c];
        q += psq [k * 128 + c];
    }
    float mu  = s * invN;
    float var = fmaxf(q * invN - mu * mu, 0.f);
    float sc  = g[c] * rsqrtf(var + 1e-5f);
    scale[c] = sc;
    shift[c] = b[c] - mu * sc;
}

// ---------------------------------------------------------------------------
// Launch
// ---------------------------------------------------------------------------
extern "C" void kernel_launch(void* const* d_in, const int* in_sizes, int n_in,
                              void* d_out, int out_size) {
    const float* pts_r1 = (const float*)d_in[0];
    const float* pts_r2 = (const float*)d_in[1];
    const float* pts_r4 = (const float*)d_in[2];
    const float* feat0  = (const float*)d_in[3];
    const float* feat1  = (const float*)d_in[4];
    const float* feat2  = (const float*)d_in[5];
    const float* w3a = (const float*)d_in[6];
    const float* g3  = (const float*)d_in[7];
    const float* b3  = (const float*)d_in[8];
    const float* w3b = (const float*)d_in[9];
    const float* bb3 = (const float*)d_in[10];
    const float* w4a = (const float*)d_in[11];
    const float* g4  = (const float*)d_in[12];
    const float* b4  = (const float*)d_in[13];
    const float* w4b = (const float*)d_in[14];
    const float* bb4 = (const float*)d_in[15];

    const int B  = 2;
    const int N1 = in_sizes[0] / (3 * B);   // 8192
    const int N2 = in_sizes[1] / (3 * B);   // 4096
    const int N4 = in_sizes[2] / (3 * B);   // 2048

    float *f2i, *h3, *n3, *n3i, *h4, *psum, *psq, *scale, *shift;
    cudaGetSymbolAddress((void**)&f2i,   g_f2i);
    cudaGetSymbolAddress((void**)&h3,    g_h3);
    cudaGetSymbolAddress((void**)&n3,    g_n3);
    cudaGetSymbolAddress((void**)&n3i,   g_n3i);
    cudaGetSymbolAddress((void**)&h4,    g_h4);
    cudaGetSymbolAddress((void**)&psum,  g_psum);
    cudaGetSymbolAddress((void**)&psq,   g_psq);
    cudaGetSymbolAddress((void**)&scale, g_scale);
    cudaGetSymbolAddress((void**)&shift, g_shift);

    const int TPB = IWARPS * TPW * 32 / 32;  // targets per block = IWARPS*TPW
    (void)TPB;

    // --- fnode 3: interp feat2 (r4 grid) onto r2 grid ---
    {
        dim3 grid((N2 + IWARPS * TPW - 1) / (IWARPS * TPW), B);
        size_t shmem = (size_t)3 * N4 * sizeof(float);
        interp3nn<<<grid, 256, shmem>>>(pts_r4, pts_r2, feat2, f2i, N4, N2);
    }
    // h3 = concat(feat1, f2i) @ w3a^T   (+ BN partial sums)
    gemm128<256, true, false, true, false><<<(B * N2) / 128, 256>>>(
        feat1, f2i, w3a, nullptr, nullptr, nullptr, h3, psum, psq);
    bn_finalize<<<1, 128>>>(psum, psq, (B * N2) / 128, 1.f / (B * N2), g3, b3, scale, shift);
    // n3 = relu(BN(h3)) @ w3b^T + bb3
    gemm128<128, false, true, false, true><<<(B * N2) / 128, 256>>>(
        h3, nullptr, w3b, scale, shift, bb3, n3, nullptr, nullptr);

    // --- fnode 4: interp n3 (r2 grid) onto r1 grid ---
    {
        dim3 grid((N1 + IWARPS * TPW - 1) / (IWARPS * TPW), B);
        size_t shmem = (size_t)3 * N2 * sizeof(float);
        interp3nn<<<grid, 256, shmem>>>(pts_r2, pts_r1, n3, n3i, N2, N1);
    }
    // h4 = concat(feat0, n3i) @ w4a^T   (+ BN partial sums)
    gemm128<256, true, false, true, false><<<(B * N1) / 128, 256>>>(
        feat0, n3i, w4a, nullptr, nullptr, nullptr, h4, psum, psq);
    bn_finalize<<<1, 128>>>(psum, psq, (B * N1) / 128, 1.f / (B * N1), g4, b4, scale, shift);
    // out = relu(BN(h4)) @ w4b^T + bb4
    gemm128<128, false, true, false, true><<<(B * N1) / 128, 256>>>(
        h4, nullptr, w4b, scale, shift, bb4, (float*)d_out, nullptr, nullptr);
}

// round 3
// speedup vs baseline: 1.0460x; 1.0460x over previous
#include <cuda_runtime.h>

// ---------------------------------------------------------------------------
// PointGiraffeLayer: 3-NN interpolate -> FC(BN,ReLU) -> 3-NN interpolate -> FC
// Shapes (fixed): B=2, N1=8192, N2=4096, N4=2048, C=128
// ---------------------------------------------------------------------------

#define CCH 128

// Scratch (device globals -- no allocation allowed)
__device__ float g_f2i[2 * 4096 * CCH];
__device__ float g_h3 [2 * 4096 * CCH];
__device__ float g_n3 [2 * 4096 * CCH];
__device__ float g_n3i[2 * 8192 * CCH];
__device__ float g_h4 [2 * 8192 * CCH];
__device__ float g_psum[256 * 128];       // per-block column sums (<=256 chunks)
__device__ float g_psq [256 * 128];
__device__ float g_scale[128];
__device__ float g_shift[128];

// ---------------------------------------------------------------------------
// 3-NN interpolation. One warp handles TPW targets; sources cached in smem
// as packed float4 (x,y,z,pad) -> one LDS.128 per source.
// ---------------------------------------------------------------------------
__device__ __forceinline__ void ins3(float d, int s,
                                     float& d0, int& i0,
                                     float& d1, int& i1,
                                     float& d2, int& i2) {
    if (d < d2) {
        if (d < d1) {
            d2 = d1; i2 = i1;
            if (d < d0) { d1 = d0; i1 = i0; d0 = d; i0 = s; }
            else        { d1 = d;  i1 = s; }
        } else { d2 = d; i2 = s; }
    }
}

constexpr int IWARPS = 8;   // warps per block
constexpr int TPW    = 4;   // targets per warp

__global__ void interp3nn(const float* __restrict__ src_xyz,   // (B,NS,3)
                          const float* __restrict__ tgt_xyz,   // (B,NT,3)
                          const float* __restrict__ feats,     // (B*NS,128)
                          float* __restrict__ out,             // (B*NT,128)
                          int NS, int NT) {
    extern __shared__ float4 sp[];   // NS packed xyz

    const int b = blockIdx.y;
    const float* S = src_xyz + (size_t)b * NS * 3;
    for (int i = threadIdx.x; i < NS; i += blockDim.x) {
        float4 p;
        p.x = S[3 * i + 0];
        p.y = S[3 * i + 1];
        p.z = S[3 * i + 2];
        p.w = 0.f;
        sp[i] = p;
    }
    __syncthreads();

    const int warp = threadIdx.x >> 5;
    const int lane = threadIdx.x & 31;
    const int tbase = (blockIdx.x * IWARPS + warp) * TPW;
    if (tbase >= NT) return;

    float tx[TPW], ty[TPW], tz[TPW];
    float d0[TPW], d1[TPW], d2[TPW];
    int   i0[TPW], i1[TPW], i2[TPW];
#pragma unroll
    for (int j = 0; j < TPW; j++) {
        int t = min(tbase + j, NT - 1);
        const float* T = tgt_xyz + ((size_t)b * NT + t) * 3;
        tx[j] = T[0]; ty[j] = T[1]; tz[j] = T[2];
        d0[j] = d1[j] = d2[j] = 3.4e38f;
        i0[j] = i1[j] = i2[j] = 0;
    }

    for (int s = lane; s < NS; s += 32) {
        float4 p = sp[s];
#pragma unroll
        for (int j = 0; j < TPW; j++) {
            float dx = tx[j] - p.x, dy = ty[j] - p.y, dz = tz[j] - p.z;
            float d = dx * dx + dy * dy + dz * dz;
            ins3(d, s, d0[j], i0[j], d1[j], i1[j], d2[j], i2[j]);
        }
    }

    // butterfly merge of sorted triples across the warp
#pragma unroll
    for (int j = 0; j < TPW; j++) {
#pragma unroll
        for (int off = 16; off > 0; off >>= 1) {
            float od0 = __shfl_xor_sync(0xffffffffu, d0[j], off);
            int   oi0 = __shfl_xor_sync(0xffffffffu, i0[j], off);
            float od1 = __shfl_xor_sync(0xffffffffu, d1[j], off);
            int   oi1 = __shfl_xor_sync(0xffffffffu, i1[j], off);
            float od2 = __shfl_xor_sync(0xffffffffu, d2[j], off);
            int   oi2 = __shfl_xor_sync(0xffffffffu, i2[j], off);
            ins3(od0, oi0, d0[j], i0[j], d1[j], i1[j], d2[j], i2[j]);
            ins3(od1, oi1, d0[j], i0[j], d1[j], i1[j], d2[j], i2[j]);
            ins3(od2, oi2, d0[j], i0[j], d1[j], i1[j], d2[j], i2[j]);
        }
    }

    // weights + 3-row gather (float4 per lane: 32 lanes * 4 = 128 channels)
#pragma unroll
    for (int j = 0; j < TPW; j++) {
        int t = tbase + j;
        if (t >= NT) break;
        float s0 = sqrtf(fmaxf(d0[j], 0.f));
        float s1 = sqrtf(fmaxf(d1[j], 0.f));
        float s2 = sqrtf(fmaxf(d2[j], 0.f));
        float w0 = 1.f / (s0 + 1e-8f);
        float w1 = 1.f / (s1 + 1e-8f);
        float w2 = 1.f / (s2 + 1e-8f);
        float wi = 1.f / (w0 + w1 + w2);
        w0 *= wi; w1 *= wi; w2 *= wi;

        const float4* f0 = (const float4*)(feats + ((size_t)b * NS + i0[j]) * CCH);
        const float4* f1 = (const float4*)(feats + ((size_t)b * NS + i1[j]) * CCH);
        const float4* f2 = (const float4*)(feats + ((size_t)b * NS + i2[j]) * CCH);
        float4 a = f0[lane], bb = f1[lane], cc = f2[lane];
        float4 r;
        r.x = w0 * a.x + w1 * bb.x + w2 * cc.x;
        r.y = w0 * a.y + w1 * bb.y + w2 * cc.y;
        r.z = w0 * a.z + w1 * bb.z + w2 * cc.z;
        r.w = w0 * a.w + w1 * bb.w + w2 * cc.w;
        ((float4*)(out + ((size_t)b * NT + t) * CCH))[lane] = r;
    }
}

// ---------------------------------------------------------------------------
// Tiled SGEMM: C (N x 128) = X (N x KD) @ W^T  (W is (128, KD) row-major)
// Tile 64(M) x 128(N) x 16(K), 128 threads, 8x8 microtile -> grid = N/64
// SPLIT : X = concat(A0, A1) along K (each N x 128)
// AFFINE: x -> relu(x * scale[k] + shift[k]) applied on load (BN+ReLU fusion)
// SUMS  : emit per-block column sum / sumsq of C (pre-bias) -> BN stats
// BIAS  : add bias[col] at epilogue
// ---------------------------------------------------------------------------
template <int KD, bool SPLIT, bool AFFINE, bool SUMS, bool BIAS>
__global__ __launch_bounds__(128) void gemm128(
        const float* __restrict__ A0, const float* __restrict__ A1,
        const float* __restrict__ W,
        const float* __restrict__ scale, const float* __restrict__ shift,
        const float* __restrict__ bias,
        float* __restrict__ Cout,
        float* __restrict__ psum, float* __restrict__ psq) {
    __shared__ float As[16][64];
    __shared__ float Bs[16][128];

    const int t  = threadIdx.x;
    const int tx = t & 15;        // 16 col groups (x8 = 128 cols)
    const int ty = t >> 4;        // 8 row groups  (x8 = 64 rows)
    const int blockRow = blockIdx.x * 64;

    float acc[8][8];
#pragma unroll
    for (int i = 0; i < 8; i++)
#pragma unroll
        for (int j = 0; j < 8; j++) acc[i][j] = 0.f;

    for (int k0 = 0; k0 < KD; k0 += 16) {
        // --- load A tile (64 rows x 16 k) = 256 float4 slots, 2 per thread ---
#pragma unroll
        for (int i = 0; i < 2; i++) {
            int f   = t + i * 128;
            int row = f >> 2;
            int kq  = (f & 3) << 2;
            int kg  = k0 + kq;
            const float* src;
            if (SPLIT) {
                src = (kg < 128) ? (A0 + (size_t)(blockRow + row) * 128 + kg)
                                 : (A1 + (size_t)(blockRow + row) * 128 + (kg - 128));
            } else {
                src = A0 + (size_t)(blockRow + row) * KD + kg;
            }
            float4 v = *(const float4*)src;
            if (AFFINE) {
                v.x = fmaxf(v.x * scale[kg + 0] + shift[kg + 0], 0.f);
                v.y = fmaxf(v.y * scale[kg + 1] + shift[kg + 1], 0.f);
                v.z = fmaxf(v.z * scale[kg + 2] + shift[kg + 2], 0.f);
                v.w = fmaxf(v.w * scale[kg + 3] + shift[kg + 3], 0.f);
            }
            As[kq + 0][row] = v.x;
            As[kq + 1][row] = v.y;
            As[kq + 2][row] = v.z;
            As[kq + 3][row] = v.w;
        }
        // --- load B tile (W^T, 128 oc x 16 k) = 512 float4 slots, 4/thread ---
#pragma unroll
        for (int i = 0; i < 4; i++) {
            int f  = t + i * 128;
            int oc = f >> 2;
            int kq = (f & 3) << 2;
            float4 v = *(const float4*)(W + (size_t)oc * KD + k0 + kq);
            Bs[kq + 0][oc] = v.x;
            Bs[kq + 1][oc] = v.y;
            Bs[kq + 2][oc] = v.z;
            Bs[kq + 3][oc] = v.w;
        }
        __syncthreads();

#pragma unroll
        for (int k = 0; k < 16; k++) {
            float4 a0 = *(const float4*)&As[k][ty * 8];
            float4 a1 = *(const float4*)&As[k][ty * 8 + 4];
            float4 b0 = *(const float4*)&Bs[k][tx * 8];
            float4 b1 = *(const float4*)&Bs[k][tx * 8 + 4];
            float ar[8] = {a0.x, a0.y, a0.z, a0.w, a1.x, a1.y, a1.z, a1.w};
            float br[8] = {b0.x, b0.y, b0.z, b0.w, b1.x, b1.y, b1.z, b1.w};
#pragma unroll
            for (int i = 0; i < 8; i++)
#pragma unroll
                for (int j = 0; j < 8; j++) acc[i][j] += ar[i] * br[j];
        }
        __syncthreads();
    }

    // --- epilogue: store ---
    const int r0 = blockRow + ty * 8;
    const int c0 = tx * 8;
#pragma unroll
    for (int i = 0; i < 8; i++) {
        float4 v0, v1;
        v0.x = acc[i][0]; v0.y = acc[i][1]; v0.z = acc[i][2]; v0.w = acc[i][3];
        v1.x = acc[i][4]; v1.y = acc[i][5]; v1.z = acc[i][6]; v1.w = acc[i][7];
        if (BIAS) {
            v0.x += bias[c0 + 0]; v0.y += bias[c0 + 1]; v0.z += bias[c0 + 2]; v0.w += bias[c0 + 3];
            v1.x += bias[c0 + 4]; v1.y += bias[c0 + 5]; v1.z += bias[c0 + 6]; v1.w += bias[c0 + 7];
        }
        *(float4*)(Cout + (size_t)(r0 + i) * 128 + c0)     = v0;
        *(float4*)(Cout + (size_t)(r0 + i) * 128 + c0 + 4) = v1;
    }

    // --- deterministic per-block BN partials (pre-bias values) ---
    if (SUMS) {
        float cs[8], cq[8];
#pragma unroll
        for (int j = 0; j < 8; j++) {
            float s = 0.f, q = 0.f;
#pragma unroll
            for (int i = 0; i < 8; i++) { s += acc[i][j]; q += acc[i][j] * acc[i][j]; }
            cs[j] = s; cq[j] = q;
        }
        float* red = &As[0][0];   // reuse: 8 x 128 = 1024 floats (exactly As size)
        __syncthreads();
#pragma unroll
        for (int j = 0; j < 8; j++) red[ty * 128 + c0 + j] = cs[j];
        __syncthreads();
        {
            float s = 0.f;          // t < 128 always (blockDim = 128)
#pragma unroll
            for (int y = 0; y < 8; y++) s += red[y * 128 + t];
            psum[blockIdx.x * 128 + t] = s;
        }
        __syncthreads();
#pragma unroll
        for (int j = 0; j < 8; j++) red[ty * 128 + c0 + j] = cq[j];
        __syncthreads();
        {
            float s = 0.f;
#pragma unroll
            for (int y = 0; y < 8; y++) s += red[y * 128 + t];
            psq[blockIdx.x * 128 + t] = s;
        }
    }
}

// ---------------------------------------------------------------------------
// BN finalize: mean/var from partials -> (scale, shift) for fused affine+ReLU
// ---------------------------------------------------------------------------
__global__ void bn_finalize(const float* __restrict__ psum, const float* __restrict__ psq,
                            int nchunks, float invN,
                            const float* __restrict__ g, const float* __restrict__ b,
                            float* __restrict__ scale, float* __restrict__ shift) {
    int c = threadIdx.x;
    float s = 0.f, q = 0.f;
    for (int k = 0; k < nchunks; k++) {
        s += psum[k * 128 + c];
        q += psq [k * 128 + c];
    }
    float mu  = s * invN;
    float var = fmaxf(q * invN - mu * mu, 0.f);
    float sc  = g[c] * rsqrtf(var + 1e-5f);
    scale[c] = sc;
    shift[c] = b[c] - mu * sc;
}

// ---------------------------------------------------------------------------
// Launch
// ---------------------------------------------------------------------------
extern "C" void kernel_launch(void* const* d_in, const int* in_sizes, int n_in,
                              void* d_out, int out_size) {
    const float* pts_r1 = (const float*)d_in[0];
    const float* pts_r2 = (const float*)d_in[1];
    const float* pts_r4 = (const float*)d_in[2];
    const float* feat0  = (const float*)d_in[3];
    const float* feat1  = (const float*)d_in[4];
    const float* feat2  = (const float*)d_in[5];
    const float* w3a = (const float*)d_in[6];
    const float* g3  = (const float*)d_in[7];
    const float* b3  = (const float*)d_in[8];
    const float* w3b = (const float*)d_in[9];
    const float* bb3 = (const float*)d_in[10];
    const float* w4a = (const float*)d_in[11];
    const float* g4  = (const float*)d_in[12];
    const float* b4  = (const float*)d_in[13];
    const float* w4b = (const float*)d_in[14];
    const float* bb4 = (const float*)d_in[15];

    const int B  = 2;
    const int N1 = in_sizes[0] / (3 * B);   // 8192
    const int N2 = in_sizes[1] / (3 * B);   // 4096
    const int N4 = in_sizes[2] / (3 * B);   // 2048

    float *f2i, *h3, *n3, *n3i, *h4, *psum, *psq, *scale, *shift;
    cudaGetSymbolAddress((void**)&f2i,   g_f2i);
    cudaGetSymbolAddress((void**)&h3,    g_h3);
    cudaGetSymbolAddress((void**)&n3,    g_n3);
    cudaGetSymbolAddress((void**)&n3i,   g_n3i);
    cudaGetSymbolAddress((void**)&h4,    g_h4);
    cudaGetSymbolAddress((void**)&psum,  g_psum);
    cudaGetSymbolAddress((void**)&psq,   g_psq);
    cudaGetSymbolAddress((void**)&scale, g_scale);
    cudaGetSymbolAddress((void**)&shift, g_shift);

    // allow >48KB dynamic smem for the 4096-source interp (64KB)
    cudaFuncSetAttribute(interp3nn, cudaFuncAttributeMaxDynamicSharedMemorySize,
                         (int)(4096 * sizeof(float4)));

    // --- fnode 3: interp feat2 (r4 grid) onto r2 grid ---
    {
        dim3 grid((N2 + IWARPS * TPW - 1) / (IWARPS * TPW), B);
        size_t shmem = (size_t)N4 * sizeof(float4);
        interp3nn<<<grid, 256, shmem>>>(pts_r4, pts_r2, feat2, f2i, N4, N2);
    }
    // h3 = concat(feat1, f2i) @ w3a^T   (+ BN partial sums)
    gemm128<256, true, false, true, false><<<(B * N2) / 64, 128>>>(
        feat1, f2i, w3a, nullptr, nullptr, nullptr, h3, psum, psq);
    bn_finalize<<<1, 128>>>(psum, psq, (B * N2) / 64, 1.f / (B * N2), g3, b3, scale, shift);
    // n3 = relu(BN(h3)) @ w3b^T + bb3
    gemm128<128, false, true, false, true><<<(B * N2) / 64, 128>>>(
        h3, nullptr, w3b, scale, shift, bb3, n3, nullptr, nullptr);

    // --- fnode 4: interp n3 (r2 grid) onto r1 grid ---
    {
        dim3 grid((N1 + IWARPS * TPW - 1) / (IWARPS * TPW), B);
        size_t shmem = (size_t)N2 * sizeof(float4);
        interp3nn<<<grid, 256, shmem>>>(pts_r2, pts_r1, n3, n3i, N2, N1);
    }
    // h4 = concat(feat0, n3i) @ w4a^T   (+ BN partial sums)
    gemm128<256, true, false, true, false><<<(B * N1) / 64, 128>>>(
        feat0, n3i, w4a, nullptr, nullptr, nullptr, h4, psum, psq);
    bn_finalize<<<1, 128>>>(psum, psq, (B * N1) / 64, 1.f / (B * N1), g4, b4, scale, shift);
    // out = relu(BN(h4)) @ w4b^T + bb4
    gemm128<128, false, true, false, true><<<(B * N1) / 64, 128>>>(
        h4, nullptr, w4b, scale, shift, bb4, (float*)d_out, nullptr, nullptr);
}